// round 1
// baseline (speedup 1.0000x reference)
#include <cuda_runtime.h>
#include <cuda_bf16.h>
#include <cstdint>

// HashGridEncoding: P points x L levels, dense multi-res grid, trilinear interp.
// L=9, T=2^21, F=2, domain [-1,1]. Flat index = ix + iy*v + iz*v^2 (NO level
// offset -- matches reference exactly).
//
// Decomposition: 1 thread per (point, level). blockDim=288 -> 32 points/block,
// lanes l=0..8 of a point write contiguous 72B output rows. 8 independent
// float2 gathers per thread (MLP=8).

#define NUM_LEVELS 9

__global__ void __launch_bounds__(288) hashgrid_kernel(
    const float* __restrict__ x,
    const float* __restrict__ table,
    float* __restrict__ out,
    int P)
{
    int tid = blockIdx.x * blockDim.x + threadIdx.x;
    int p = tid / NUM_LEVELS;
    int l = tid - p * NUM_LEVELS;
    if (p >= P) return;

    // Load point coords (9 lanes share -> L1 broadcast)
    float px = __ldg(&x[p * 3 + 0]);
    float py = __ldg(&x[p * 3 + 1]);
    float pz = __ldg(&x[p * 3 + 2]);

    int   vi = 1 << l;
    float vf = (float)vi;

    // norm in [0,1), g in [0, v)
    float gx = (px + 1.0f) * 0.5f * vf;
    float gy = (py + 1.0f) * 0.5f * vf;
    float gz = (pz + 1.0f) * 0.5f * vf;

    float bxf = floorf(gx);
    float byf = floorf(gy);
    float bzf = floorf(gz);

    float fx = gx - bxf;
    float fy = gy - byf;
    float fz = gz - bzf;

    int ix = (int)bxf;
    int iy = (int)byf;
    int iz = (int)bzf;

    int flat = ix + iy * vi + iz * vi * vi;
    int dz = vi * vi;

    const float2* __restrict__ tab = (const float2*)table;

    // 8 corners: bit0 -> +1 (x), bit1 -> +vi (y), bit2 -> +vi^2 (z)
    float2 q000 = __ldg(&tab[flat]);
    float2 q100 = __ldg(&tab[flat + 1]);
    float2 q010 = __ldg(&tab[flat + vi]);
    float2 q110 = __ldg(&tab[flat + vi + 1]);
    float2 q001 = __ldg(&tab[flat + dz]);
    float2 q101 = __ldg(&tab[flat + dz + 1]);
    float2 q011 = __ldg(&tab[flat + dz + vi]);
    float2 q111 = __ldg(&tab[flat + dz + vi + 1]);

    float wx0 = 1.0f - fx, wx1 = fx;
    float wy0 = 1.0f - fy, wy1 = fy;
    float wz0 = 1.0f - fz, wz1 = fz;

    // x-lerps
    float a0x = wx0 * q000.x + wx1 * q100.x;
    float a0y = wx0 * q000.y + wx1 * q100.y;
    float a1x = wx0 * q010.x + wx1 * q110.x;
    float a1y = wx0 * q010.y + wx1 * q110.y;
    float a2x = wx0 * q001.x + wx1 * q101.x;
    float a2y = wx0 * q001.y + wx1 * q101.y;
    float a3x = wx0 * q011.x + wx1 * q111.x;
    float a3y = wx0 * q011.y + wx1 * q111.y;

    // y-lerps
    float b0x = wy0 * a0x + wy1 * a1x;
    float b0y = wy0 * a0y + wy1 * a1y;
    float b1x = wy0 * a2x + wy1 * a3x;
    float b1y = wy0 * a2y + wy1 * a3y;

    // z-lerp
    float rx = wz0 * b0x + wz1 * b1x;
    float ry = wz0 * b0y + wz1 * b1y;

    // out[p, l*2 + {0,1}]
    float2* __restrict__ o2 = (float2*)out;
    o2[p * NUM_LEVELS + l] = make_float2(rx, ry);
}

extern "C" void kernel_launch(void* const* d_in, const int* in_sizes, int n_in,
                              void* d_out, int out_size)
{
    const float* x     = (const float*)d_in[0];
    const float* table = (const float*)d_in[1];
    float* out         = (float*)d_out;

    int P = in_sizes[0] / 3;
    int total = P * NUM_LEVELS;
    int threads = 288;                 // 32 points per block
    int blocks = (total + threads - 1) / threads;
    hashgrid_kernel<<<blocks, threads>>>(x, table, out, P);
}